// round 12
// baseline (speedup 1.0000x reference)
#include <cuda_runtime.h>
#include <cuda_fp16.h>
#include <math.h>
#include <stdint.h>

// Problem constants
#define B_SZ   8
#define N_SEQ  1024
#define C_DIM  768
#define H_HEAD 12
#define D_HEAD 64
#define QKV_LD 2304            // 3*C
#define SCALE  0.125f          // 64^-0.5

// Scratch (allocation-free: __device__ globals). GEMM operands fp16, acc fp32.
__device__ __half g_xh[(size_t)B_SZ * N_SEQ * C_DIM];
__device__ __half g_qkv[(size_t)B_SZ * N_SEQ * 3 * C_DIM];            // [8192, 2304]
__device__ float  g_scores[(size_t)B_SZ * H_HEAD * N_SEQ * N_SEQ];    // [96,1024,1024] fp32
__device__ __half g_attn[(size_t)B_SZ * H_HEAD * N_SEQ * N_SEQ];      // [96,1024,1024] fp16
__device__ __half g_av[(size_t)B_SZ * N_SEQ * C_DIM];                 // [8192, 768]
__device__ __half g_vT[(size_t)B_SZ * H_HEAD * D_HEAD * N_SEQ];       // [96, 64, 1024]
__device__ __half g_wqkvT[(size_t)3 * C_DIM * C_DIM];                 // [2304, 768]
__device__ __half g_wprojT[(size_t)C_DIM * C_DIM];                    // [768, 768]

// ---------------------------------------------------------------------------
// helpers
// ---------------------------------------------------------------------------
__device__ __forceinline__ void cpa16(unsigned s, const void* g) {
    asm volatile("cp.async.cg.shared.global [%0], [%1], 16;" :: "r"(s), "l"(g));
}
#define CPA_COMMIT() asm volatile("cp.async.commit_group;")
#define CPA_WAIT(n)  asm volatile("cp.async.wait_group %0;" :: "n"(n))

__device__ __forceinline__ uint32_t pack_h2(float a, float b) {
    __half2 h = __floats2half2_rn(a, b);
    return *reinterpret_cast<uint32_t*>(&h);
}

#define MMA_F16(d, a, b)                                                      \
    asm volatile(                                                             \
        "mma.sync.aligned.m16n8k16.row.col.f32.f16.f16.f32 "                  \
        "{%0,%1,%2,%3}, {%4,%5,%6,%7}, {%8,%9}, {%0,%1,%2,%3};"               \
        : "+f"(d[0]), "+f"(d[1]), "+f"(d[2]), "+f"(d[3])                      \
        : "r"(a[0]), "r"(a[1]), "r"(a[2]), "r"(a[3]), "r"(b[0]), "r"(b[1]))

#define LDSM4(r0, r1, r2, r3, addr)                                           \
    asm volatile(                                                             \
        "ldmatrix.sync.aligned.m8n8.x4.shared.b16 {%0,%1,%2,%3}, [%4];"       \
        : "=r"(r0), "=r"(r1), "=r"(r2), "=r"(r3) : "r"(addr))

// ---------------------------------------------------------------------------
// fp16 NT GEMM: C[M,N] = scale * (A[M,K] @ B[N,K]^T) + bias[N]
// BM=128, BK=32, 256 threads (8 warps 4x2), warp tile 32 x (BN/2),
// mma m16n8k16 (fp16 in, fp32 acc), 3-stage cp.async pipeline (2 in flight),
// ldmatrix.x4 fragment loads (conflict-free on pad-40 rows).
// __launch_bounds__(256, 3): 3 CTAs/SM (85-reg cap, 60KB smem @ BN=128).
// OUT_HALF: C stored as __half else fp32.
// ---------------------------------------------------------------------------
template<int BN, bool OUT_HALF>
__global__ __launch_bounds__(256, 3) void gemm_f16(
    const __half* __restrict__ Ag, const __half* __restrict__ Bg,
    const float* __restrict__ bias, void* __restrict__ Cg,
    int K, int lda, int ldb, int ldc,
    long long az1, long long az2, long long bz1, long long bz2,
    long long cz1, long long cz2, float scale)
{
    constexpr int WN = BN / 2;
    constexpr int NI = WN / 8;
    constexpr int NP = NI / 2;            // B ldmatrix pairs
    constexpr int ASTG = 128 * 40;        // halves per A stage
    constexpr int BSTG = BN * 40;
    constexpr int NSTG = 3;

    extern __shared__ __half sh[];
    const uint32_t sb = (uint32_t)__cvta_generic_to_shared(sh);
    const uint32_t sbB = sb + NSTG * ASTG * 2;

    const int tid = threadIdx.x;
    const int lane = tid & 31, warp = tid >> 5;
    const int wm = warp & 3, wn = warp >> 2;
    const int g = lane >> 2, tg = lane & 3;

    const int z = blockIdx.z;
    const int zb = z / H_HEAD, zh = z % H_HEAD;
    const __half* A = Ag + zb * az1 + zh * az2 + (size_t)blockIdx.y * 128 * lda;
    const __half* B = Bg + zb * bz1 + zh * bz2 + (size_t)blockIdx.x * BN * ldb;

    const int lr = tid >> 2;              // cp.async chunk row
    const int lc = (tid & 3) << 3;        // cp.async chunk col (halves)

    // ldmatrix per-lane byte offsets within a stage.
    uint32_t aOff[2];
#pragma unroll
    for (int mi = 0; mi < 2; mi++)
        aOff[mi] = ((wm * 32 + mi * 16 + (lane & 15)) * 40 + (lane >> 4) * 8) * 2;
    uint32_t bOff[NP];
#pragma unroll
    for (int p = 0; p < NP; p++)
        bOff[p] = ((wn * WN + p * 16 + (lane & 7) + ((lane >> 4) & 1) * 8) * 40 +
                   ((lane >> 3) & 1) * 8) * 2;

    float acc[2][NI][4];
#pragma unroll
    for (int mi = 0; mi < 2; mi++)
#pragma unroll
        for (int ni = 0; ni < NI; ni++)
#pragma unroll
            for (int j = 0; j < 4; j++) acc[mi][ni][j] = 0.f;

    const int niter = K >> 5;

    auto stage_load = [&](int st, int k0) {
#pragma unroll
        for (int l = 0; l < 2; l++) {
            int r = lr + l * 64;
            cpa16(sb + (st * ASTG + r * 40 + lc) * 2, A + (size_t)r * lda + k0 + lc);
        }
#pragma unroll
        for (int l = 0; l < BN / 64; l++) {
            int r = lr + l * 64;
            cpa16(sbB + (st * BSTG + r * 40 + lc) * 2, B + (size_t)r * ldb + k0 + lc);
        }
        CPA_COMMIT();
    };

    // 3-stage: preload 2 chunks; at iter i (after barrier) load chunk i+2 into
    // stage (i+2)%3 — that stage was consumed at iter i-1, barrier-protected.
    stage_load(0, 0);
    if (niter > 1) stage_load(1, 32);

    int st = 0;
    for (int i = 0; i < niter; i++) {
        // commits = min(2+i, niter); chunk i complete iff pending <=
        // min(1, niter-i-1). Tail drains fully (R6 ladder).
        if (i + 1 < niter) { CPA_WAIT(1); } else { CPA_WAIT(0); }
        __syncthreads();
        int nld = i + 2;
        if (nld < niter) {
            int ls = nld - (nld / 3) * 3;
            stage_load(ls, nld << 5);
        }

        const uint32_t aS = sb + st * ASTG * 2;
        const uint32_t bS = sbB + st * BSTG * 2;
#pragma unroll
        for (int kk = 0; kk < 2; kk++) {               // kk half: +32 bytes
            unsigned a[2][4], b[NI][2];
#pragma unroll
            for (int mi = 0; mi < 2; mi++)
                LDSM4(a[mi][0], a[mi][1], a[mi][2], a[mi][3],
                      aS + aOff[mi] + kk * 32);
#pragma unroll
            for (int p = 0; p < NP; p++)
                LDSM4(b[2 * p][0], b[2 * p][1], b[2 * p + 1][0], b[2 * p + 1][1],
                      bS + bOff[p] + kk * 32);
#pragma unroll
            for (int mi = 0; mi < 2; mi++)
#pragma unroll
                for (int ni = 0; ni < NI; ni++)
                    MMA_F16(acc[mi][ni], a[mi], b[ni]);
        }
        st++; if (st == 3) st = 0;
    }

    // epilogue
    const int row_base = blockIdx.y * 128 + wm * 32;
    const int col_base = blockIdx.x * BN + wn * WN;
#pragma unroll
    for (int mi = 0; mi < 2; mi++) {
#pragma unroll
        for (int ni = 0; ni < NI; ni++) {
            int r0 = row_base + mi * 16 + g;
            int c = col_base + ni * 8 + 2 * tg;
            float b0 = 0.f, b1 = 0.f;
            if (bias) { b0 = bias[c]; b1 = bias[c + 1]; }
            float e00 = acc[mi][ni][0] * scale + b0;
            float e01 = acc[mi][ni][1] * scale + b1;
            float e10 = acc[mi][ni][2] * scale + b0;
            float e11 = acc[mi][ni][3] * scale + b1;
            if (OUT_HALF) {
                __half* C = (__half*)Cg + zb * cz1 + zh * cz2;
                *reinterpret_cast<uint32_t*>(C + (size_t)r0 * ldc + c) = pack_h2(e00, e01);
                *reinterpret_cast<uint32_t*>(C + (size_t)(r0 + 8) * ldc + c) = pack_h2(e10, e11);
            } else {
                float* C = (float*)Cg + zb * cz1 + zh * cz2;
                *reinterpret_cast<float2*>(C + (size_t)r0 * ldc + c) = make_float2(e00, e01);
                *reinterpret_cast<float2*>(C + (size_t)(r0 + 8) * ldc + c) = make_float2(e10, e11);
            }
        }
    }
}

// ---------------------------------------------------------------------------
// elementwise fp16 round of x
// ---------------------------------------------------------------------------
__global__ void round_x_f16(const float* __restrict__ in, __half* __restrict__ out)
{
    int i = blockIdx.x * 256 + threadIdx.x;
    float4 v = reinterpret_cast<const float4*>(in)[i];
    uint2 p;
    p.x = pack_h2(v.x, v.y);
    p.y = pack_h2(v.z, v.w);
    reinterpret_cast<uint2*>(out)[i] = p;
}

// ---------------------------------------------------------------------------
// 32x32 tiled transpose fp32 -> fp16
// ---------------------------------------------------------------------------
__global__ void transpose2d(const float* __restrict__ in, __half* __restrict__ out,
                            int R, int Cc)
{
    __shared__ float t[32][33];
    int c0 = blockIdx.x * 32, r0 = blockIdx.y * 32;
    int x = threadIdx.x, y = threadIdx.y;
#pragma unroll
    for (int i = 0; i < 4; i++)
        t[y + i * 8][x] = in[(size_t)(r0 + y + i * 8) * Cc + c0 + x];
    __syncthreads();
#pragma unroll
    for (int i = 0; i < 4; i++)
        out[(size_t)(c0 + y + i * 8) * R + r0 + x] = __float2half_rn(t[x][y + i * 8]);
}

// V slice of g_qkv (half) -> g_vT[z][d][m] (half)
__global__ void transpose_v()
{
    __shared__ float t[32][33];
    int z = blockIdx.z;
    int b = z / H_HEAD, h = z % H_HEAD;
    const __half* in = g_qkv + (size_t)b * N_SEQ * QKV_LD + 2 * C_DIM + h * D_HEAD;
    __half* out = g_vT + (size_t)z * D_HEAD * N_SEQ;
    int m0 = blockIdx.x * 32, d0 = blockIdx.y * 32;
    int x = threadIdx.x, y = threadIdx.y;
#pragma unroll
    for (int i = 0; i < 4; i++)
        t[y + i * 8][x] = __half2float(in[(size_t)(m0 + y + i * 8) * QKV_LD + d0 + x]);
    __syncthreads();
#pragma unroll
    for (int i = 0; i < 4; i++)
        out[(size_t)(d0 + y + i * 8) * N_SEQ + m0 + x] = __float2half_rn(t[x][y + i * 8]);
}

// ---------------------------------------------------------------------------
// Fused pre-mix (w_l) -> softmax over m -> post-mix (w_w).
// Reads fp32 g_scores; writes fp16 g_attn. One CTA per (b, n).
// ---------------------------------------------------------------------------
__global__ __launch_bounds__(256) void mixsoftmax_kernel(
    const float* __restrict__ w_l, const float* __restrict__ b_l,
    const float* __restrict__ w_w, const float* __restrict__ b_w)
{
    __shared__ float swl[144], sww[144], sbl[12], sbw[12];
    __shared__ float red[8][12];
    const int tid = threadIdx.x;
    if (tid < 144) { swl[tid] = w_l[tid]; sww[tid] = w_w[tid]; }
    if (tid < 12)  { sbl[tid] = b_l[tid]; sbw[tid] = b_w[tid]; }
    __syncthreads();

    const int bn = blockIdx.x;
    const int b = bn >> 10, n = bn & 1023;
    const size_t base = ((size_t)b * H_HEAD * N_SEQ + n) * N_SEQ;
    const int m0 = tid * 4;
    const int lane = tid & 31, wid = tid >> 5;

    float t[12][4];
#pragma unroll
    for (int g = 0; g < 12; g++) {
        float bl = sbl[g];
        t[g][0] = bl; t[g][1] = bl; t[g][2] = bl; t[g][3] = bl;
    }
#pragma unroll
    for (int h = 0; h < 12; h++) {
        float4 s4 = *reinterpret_cast<const float4*>(g_scores + base + (size_t)h * N_SEQ * N_SEQ + m0);
#pragma unroll
        for (int g = 0; g < 12; g++) {
            float wl = swl[h * 12 + g];
            t[g][0] = fmaf(s4.x, wl, t[g][0]);
            t[g][1] = fmaf(s4.y, wl, t[g][1]);
            t[g][2] = fmaf(s4.z, wl, t[g][2]);
            t[g][3] = fmaf(s4.w, wl, t[g][3]);
        }
    }

    float lmax[12];
#pragma unroll
    for (int g = 0; g < 12; g++) {
        float v = fmaxf(fmaxf(t[g][0], t[g][1]), fmaxf(t[g][2], t[g][3]));
#pragma unroll
        for (int o = 16; o > 0; o >>= 1) v = fmaxf(v, __shfl_xor_sync(0xffffffffu, v, o));
        if (lane == 0) red[wid][g] = v;
    }
    __syncthreads();
#pragma unroll
    for (int g = 0; g < 12; g++) {
        float v = red[0][g];
#pragma unroll
        for (int w = 1; w < 8; w++) v = fmaxf(v, red[w][g]);
        lmax[g] = v;
    }
    __syncthreads();

    float lsum[12];
#pragma unroll
    for (int g = 0; g < 12; g++) {
        t[g][0] = __expf(t[g][0] - lmax[g]);
        t[g][1] = __expf(t[g][1] - lmax[g]);
        t[g][2] = __expf(t[g][2] - lmax[g]);
        t[g][3] = __expf(t[g][3] - lmax[g]);
        float v = (t[g][0] + t[g][1]) + (t[g][2] + t[g][3]);
#pragma unroll
        for (int o = 16; o > 0; o >>= 1) v += __shfl_xor_sync(0xffffffffu, v, o);
        if (lane == 0) red[wid][g] = v;
    }
    __syncthreads();
#pragma unroll
    for (int g = 0; g < 12; g++) {
        float v = red[0][g];
#pragma unroll
        for (int w = 1; w < 8; w++) v += red[w][g];
        lsum[g] = 1.0f / v;
    }

#pragma unroll
    for (int g = 0; g < 12; g++) {
        t[g][0] *= lsum[g]; t[g][1] *= lsum[g]; t[g][2] *= lsum[g]; t[g][3] *= lsum[g];
    }

#pragma unroll
    for (int g = 0; g < 12; g++) {
        float o0 = sbw[g], o1 = sbw[g], o2 = sbw[g], o3 = sbw[g];
#pragma unroll
        for (int h = 0; h < 12; h++) {
            float ww = sww[h * 12 + g];
            o0 = fmaf(t[h][0], ww, o0);
            o1 = fmaf(t[h][1], ww, o1);
            o2 = fmaf(t[h][2], ww, o2);
            o3 = fmaf(t[h][3], ww, o3);
        }
        uint2 p;
        p.x = pack_h2(o0, o1);
        p.y = pack_h2(o2, o3);
        *reinterpret_cast<uint2*>(g_attn + base + (size_t)g * N_SEQ * N_SEQ + m0) = p;
    }
}

// ---------------------------------------------------------------------------
extern "C" void kernel_launch(void* const* d_in, const int* in_sizes, int n_in,
                              void* d_out, int out_size)
{
    const float* x      = (const float*)d_in[0];
    const float* w_qkv  = (const float*)d_in[1];
    const float* b_qkv  = (const float*)d_in[2];
    const float* w_l    = (const float*)d_in[3];
    const float* b_l    = (const float*)d_in[4];
    const float* w_w    = (const float*)d_in[5];
    const float* b_w    = (const float*)d_in[6];
    const float* w_proj = (const float*)d_in[7];
    const float* b_proj = (const float*)d_in[8];
    float* out = (float*)d_out;

    __half *xh_p, *qkv_p, *attn_p, *av_p, *vT_p, *wqkvT_p, *wprojT_p;
    float *scores_p;
    cudaGetSymbolAddress((void**)&xh_p, g_xh);
    cudaGetSymbolAddress((void**)&qkv_p, g_qkv);
    cudaGetSymbolAddress((void**)&scores_p, g_scores);
    cudaGetSymbolAddress((void**)&attn_p, g_attn);
    cudaGetSymbolAddress((void**)&av_p, g_av);
    cudaGetSymbolAddress((void**)&vT_p, g_vT);
    cudaGetSymbolAddress((void**)&wqkvT_p, g_wqkvT);
    cudaGetSymbolAddress((void**)&wprojT_p, g_wprojT);

    // dynamic smem: 3 stages * (128 + BN) rows * 40 halves * 2 bytes
    const int smem128 = 3 * (128 + 128) * 40 * 2;   // 61440 -> 3 CTAs/SM
    const int smem64  = 3 * (128 + 64) * 40 * 2;    // 46080
    cudaFuncSetAttribute(gemm_f16<128, true >, cudaFuncAttributeMaxDynamicSharedMemorySize, smem128);
    cudaFuncSetAttribute(gemm_f16<128, false>, cudaFuncAttributeMaxDynamicSharedMemorySize, smem128);
    cudaFuncSetAttribute(gemm_f16<64,  true >, cudaFuncAttributeMaxDynamicSharedMemorySize, smem64);

    // 0) fp16 conversions: x, transposed weights
    round_x_f16<<<(B_SZ * N_SEQ * C_DIM / 4) / 256, 256>>>(x, xh_p);
    transpose2d<<<dim3(QKV_LD / 32, C_DIM / 32), dim3(32, 8)>>>(w_qkv, wqkvT_p, C_DIM, QKV_LD);
    transpose2d<<<dim3(C_DIM / 32, C_DIM / 32), dim3(32, 8)>>>(w_proj, wprojT_p, C_DIM, C_DIM);

    const long long QB = (long long)N_SEQ * QKV_LD;
    const long long SH = (long long)N_SEQ * N_SEQ;
    const long long VH = (long long)D_HEAD * N_SEQ;

    // 1) QKV projection: [8192,768] @ wqkvT^T + bias -> fp16 qkv
    gemm_f16<128, true><<<dim3(QKV_LD / 128, B_SZ * N_SEQ / 128, 1), 256, smem128>>>(
        xh_p, wqkvT_p, b_qkv, qkv_p, C_DIM, C_DIM, C_DIM, QKV_LD,
        0, 0, 0, 0, 0, 0, 1.0f);

    // 2) transpose V slices into g_vT[z][d][m]
    transpose_v<<<dim3(N_SEQ / 32, D_HEAD / 32, B_SZ * H_HEAD), dim3(32, 8)>>>();

    // 3) scores = SCALE * q @ k^T per (b,h) -> raw fp32 (full batch, z=96)
    gemm_f16<128, false><<<dim3(N_SEQ / 128, N_SEQ / 128, B_SZ * H_HEAD), 256, smem128>>>(
        qkv_p, qkv_p + C_DIM, nullptr, scores_p, D_HEAD, QKV_LD, QKV_LD, N_SEQ,
        QB, D_HEAD, QB, D_HEAD, H_HEAD * SH, SH, SCALE);

    // 4) fused talking-heads pre-mix + softmax + post-mix -> fp16 attn
    mixsoftmax_kernel<<<B_SZ * N_SEQ, 256>>>(w_l, b_l, w_w, b_w);

    // 5) av = attn @ vT^T -> fp16 av (full batch, z=96)
    gemm_f16<64, true><<<dim3(1, N_SEQ / 128, B_SZ * H_HEAD), 256, smem64>>>(
        attn_p, vT_p, nullptr, av_p, N_SEQ, N_SEQ, N_SEQ, C_DIM,
        H_HEAD * SH, SH, H_HEAD * VH, VH, (long long)N_SEQ * C_DIM, D_HEAD, 1.0f);

    // 6) out = av @ wprojT^T + bias (fp32 out)
    gemm_f16<128, false><<<dim3(C_DIM / 128, B_SZ * N_SEQ / 128, 1), 256, smem128>>>(
        av_p, wprojT_p, b_proj, out, C_DIM, C_DIM, C_DIM, C_DIM,
        0, 0, 0, 0, 0, 0, 1.0f);
}

// round 13
// speedup vs baseline: 1.1496x; 1.1496x over previous
#include <cuda_runtime.h>
#include <cuda_fp16.h>
#include <math.h>
#include <stdint.h>

// Problem constants
#define B_SZ   8
#define N_SEQ  1024
#define C_DIM  768
#define H_HEAD 12
#define D_HEAD 64
#define QKV_LD 2304            // 3*C
#define SCALE  0.125f          // 64^-0.5

// Scratch (allocation-free: __device__ globals). GEMM operands fp16, acc fp32.
__device__ __half g_xh[(size_t)B_SZ * N_SEQ * C_DIM];
__device__ __half g_qkv[(size_t)B_SZ * N_SEQ * 3 * C_DIM];            // [8192, 2304]
__device__ float  g_scores[(size_t)B_SZ * H_HEAD * N_SEQ * N_SEQ];    // [96,1024,1024] fp32
__device__ __half g_attn[(size_t)B_SZ * H_HEAD * N_SEQ * N_SEQ];      // [96,1024,1024] fp16
__device__ __half g_av[(size_t)B_SZ * N_SEQ * C_DIM];                 // [8192, 768]
__device__ __half g_vT[(size_t)B_SZ * H_HEAD * D_HEAD * N_SEQ];       // [96, 64, 1024]
__device__ __half g_wqkvT[(size_t)3 * C_DIM * C_DIM];                 // [2304, 768]
__device__ __half g_wprojT[(size_t)C_DIM * C_DIM];                    // [768, 768]

// ---------------------------------------------------------------------------
// helpers
// ---------------------------------------------------------------------------
__device__ __forceinline__ void cpa16(unsigned s, const void* g) {
    asm volatile("cp.async.cg.shared.global [%0], [%1], 16;" :: "r"(s), "l"(g));
}
#define CPA_COMMIT() asm volatile("cp.async.commit_group;")
#define CPA_WAIT(n)  asm volatile("cp.async.wait_group %0;" :: "n"(n))

__device__ __forceinline__ uint32_t pack_h2(float a, float b) {
    __half2 h = __floats2half2_rn(a, b);
    return *reinterpret_cast<uint32_t*>(&h);
}

#define MMA_F16(d, a, b)                                                      \
    asm volatile(                                                             \
        "mma.sync.aligned.m16n8k16.row.col.f32.f16.f16.f32 "                  \
        "{%0,%1,%2,%3}, {%4,%5,%6,%7}, {%8,%9}, {%0,%1,%2,%3};"               \
        : "+f"(d[0]), "+f"(d[1]), "+f"(d[2]), "+f"(d[3])                      \
        : "r"(a[0]), "r"(a[1]), "r"(a[2]), "r"(a[3]), "r"(b[0]), "r"(b[1]))

#define LDSM4(r0, r1, r2, r3, addr)                                           \
    asm volatile(                                                             \
        "ldmatrix.sync.aligned.m8n8.x4.shared.b16 {%0,%1,%2,%3}, [%4];"       \
        : "=r"(r0), "=r"(r1), "=r"(r2), "=r"(r3) : "r"(addr))

// ---------------------------------------------------------------------------
// fp16 NT GEMM: C[M,N] = scale * (A[M,K] @ B[N,K]^T) + bias[N]
// BM=128, BK=64, 256 threads (8 warps 4x2), warp tile 32 x (BN/2),
// mma m16n8k16 (fp16 in, fp32 acc), 3-stage cp.async (2 chunks in flight),
// ldmatrix.x4 fragment loads (conflict-free on pad-72 rows: stride 36 words).
// 96 regs / 2 CTAs/SM (no min-blocks cap — R12 showed the 80-reg cap spills).
// OUT_HALF: C stored as __half else fp32.
// ---------------------------------------------------------------------------
template<int BN, bool OUT_HALF>
__global__ __launch_bounds__(256) void gemm_f16(
    const __half* __restrict__ Ag, const __half* __restrict__ Bg,
    const float* __restrict__ bias, void* __restrict__ Cg,
    int K, int lda, int ldb, int ldc,
    long long az1, long long az2, long long bz1, long long bz2,
    long long cz1, long long cz2, float scale)
{
    constexpr int WN = BN / 2;
    constexpr int NI = WN / 8;
    constexpr int NP = NI / 2;            // B ldmatrix pairs
    constexpr int LROW = 72;              // 64 halves + 8 pad
    constexpr int ASTG = 128 * LROW;      // halves per A stage
    constexpr int BSTG = BN * LROW;
    constexpr int NSTG = 3;

    extern __shared__ __half sh[];
    const uint32_t sb = (uint32_t)__cvta_generic_to_shared(sh);
    const uint32_t sbB = sb + NSTG * ASTG * 2;

    const int tid = threadIdx.x;
    const int lane = tid & 31, warp = tid >> 5;
    const int wm = warp & 3, wn = warp >> 2;
    const int g = lane >> 2, tg = lane & 3;

    const int z = blockIdx.z;
    const int zb = z / H_HEAD, zh = z % H_HEAD;
    const __half* A = Ag + zb * az1 + zh * az2 + (size_t)blockIdx.y * 128 * lda;
    const __half* B = Bg + zb * bz1 + zh * bz2 + (size_t)blockIdx.x * BN * ldb;

    const int lr = tid >> 2;              // load row within 64-row group
    const int lc = (tid & 3) * 16;        // load col (halves), 2 chunks: lc, lc+8

    // ldmatrix per-lane byte offsets within a stage (kk adds 32B per 16-k group)
    uint32_t aOff[2];
#pragma unroll
    for (int mi = 0; mi < 2; mi++)
        aOff[mi] = ((wm * 32 + mi * 16 + (lane & 15)) * LROW + (lane >> 4) * 8) * 2;
    uint32_t bOff[NP];
#pragma unroll
    for (int p = 0; p < NP; p++)
        bOff[p] = ((wn * WN + p * 16 + (lane & 7) + ((lane >> 4) & 1) * 8) * LROW +
                   ((lane >> 3) & 1) * 8) * 2;

    float acc[2][NI][4];
#pragma unroll
    for (int mi = 0; mi < 2; mi++)
#pragma unroll
        for (int ni = 0; ni < NI; ni++)
#pragma unroll
            for (int j = 0; j < 4; j++) acc[mi][ni][j] = 0.f;

    const int niter = K >> 6;             // BK = 64

    auto stage_load = [&](int st, int k0) {
#pragma unroll
        for (int l = 0; l < 2; l++) {     // A: 128 rows in 2 groups of 64
            int r = lr + l * 64;
            cpa16(sb + (st * ASTG + r * LROW + lc) * 2,      A + (size_t)r * lda + k0 + lc);
            cpa16(sb + (st * ASTG + r * LROW + lc + 8) * 2,  A + (size_t)r * lda + k0 + lc + 8);
        }
#pragma unroll
        for (int l = 0; l < BN / 64; l++) {
            int r = lr + l * 64;
            cpa16(sbB + (st * BSTG + r * LROW + lc) * 2,     B + (size_t)r * ldb + k0 + lc);
            cpa16(sbB + (st * BSTG + r * LROW + lc + 8) * 2, B + (size_t)r * ldb + k0 + lc + 8);
        }
        CPA_COMMIT();
    };

    // 3-stage: preload 2 chunks; at iter i (after barrier) load chunk i+2 into
    // stage (i+2)%3 — that stage was consumed at iter i-1, barrier-protected.
    stage_load(0, 0);
    if (niter > 1) stage_load(1, 64);

    int st = 0;
    for (int i = 0; i < niter; i++) {
        // commits = min(2+i, niter); chunk i complete iff pending <=
        // min(1, niter-i-1). Tail drains fully (proven R6 ladder).
        if (i + 1 < niter) { CPA_WAIT(1); } else { CPA_WAIT(0); }
        __syncthreads();
        int nld = i + 2;
        if (nld < niter) {
            int ls = nld - (nld / 3) * 3;
            stage_load(ls, nld << 6);
        }

        const uint32_t aS = sb + st * ASTG * 2;
        const uint32_t bS = sbB + st * BSTG * 2;
#pragma unroll
        for (int kk = 0; kk < 4; kk++) {               // four 16-k groups, +32B each
            unsigned a[2][4], b[NI][2];
#pragma unroll
            for (int mi = 0; mi < 2; mi++)
                LDSM4(a[mi][0], a[mi][1], a[mi][2], a[mi][3],
                      aS + aOff[mi] + kk * 32);
#pragma unroll
            for (int p = 0; p < NP; p++)
                LDSM4(b[2 * p][0], b[2 * p][1], b[2 * p + 1][0], b[2 * p + 1][1],
                      bS + bOff[p] + kk * 32);
#pragma unroll
            for (int mi = 0; mi < 2; mi++)
#pragma unroll
                for (int ni = 0; ni < NI; ni++)
                    MMA_F16(acc[mi][ni], a[mi], b[ni]);
        }
        st++; if (st == 3) st = 0;
    }

    // epilogue
    const int row_base = blockIdx.y * 128 + wm * 32;
    const int col_base = blockIdx.x * BN + wn * WN;
#pragma unroll
    for (int mi = 0; mi < 2; mi++) {
#pragma unroll
        for (int ni = 0; ni < NI; ni++) {
            int r0 = row_base + mi * 16 + g;
            int c = col_base + ni * 8 + 2 * tg;
            float b0 = 0.f, b1 = 0.f;
            if (bias) { b0 = bias[c]; b1 = bias[c + 1]; }
            float e00 = acc[mi][ni][0] * scale + b0;
            float e01 = acc[mi][ni][1] * scale + b1;
            float e10 = acc[mi][ni][2] * scale + b0;
            float e11 = acc[mi][ni][3] * scale + b1;
            if (OUT_HALF) {
                __half* C = (__half*)Cg + zb * cz1 + zh * cz2;
                *reinterpret_cast<uint32_t*>(C + (size_t)r0 * ldc + c) = pack_h2(e00, e01);
                *reinterpret_cast<uint32_t*>(C + (size_t)(r0 + 8) * ldc + c) = pack_h2(e10, e11);
            } else {
                float* C = (float*)Cg + zb * cz1 + zh * cz2;
                *reinterpret_cast<float2*>(C + (size_t)r0 * ldc + c) = make_float2(e00, e01);
                *reinterpret_cast<float2*>(C + (size_t)(r0 + 8) * ldc + c) = make_float2(e10, e11);
            }
        }
    }
}

// ---------------------------------------------------------------------------
// elementwise fp16 round of x
// ---------------------------------------------------------------------------
__global__ void round_x_f16(const float* __restrict__ in, __half* __restrict__ out)
{
    int i = blockIdx.x * 256 + threadIdx.x;
    float4 v = reinterpret_cast<const float4*>(in)[i];
    uint2 p;
    p.x = pack_h2(v.x, v.y);
    p.y = pack_h2(v.z, v.w);
    reinterpret_cast<uint2*>(out)[i] = p;
}

// ---------------------------------------------------------------------------
// 32x32 tiled transpose fp32 -> fp16
// ---------------------------------------------------------------------------
__global__ void transpose2d(const float* __restrict__ in, __half* __restrict__ out,
                            int R, int Cc)
{
    __shared__ float t[32][33];
    int c0 = blockIdx.x * 32, r0 = blockIdx.y * 32;
    int x = threadIdx.x, y = threadIdx.y;
#pragma unroll
    for (int i = 0; i < 4; i++)
        t[y + i * 8][x] = in[(size_t)(r0 + y + i * 8) * Cc + c0 + x];
    __syncthreads();
#pragma unroll
    for (int i = 0; i < 4; i++)
        out[(size_t)(c0 + y + i * 8) * R + r0 + x] = __float2half_rn(t[x][y + i * 8]);
}

// V slice of g_qkv (half) -> g_vT[z][d][m] (half)
__global__ void transpose_v()
{
    __shared__ float t[32][33];
    int z = blockIdx.z;
    int b = z / H_HEAD, h = z % H_HEAD;
    const __half* in = g_qkv + (size_t)b * N_SEQ * QKV_LD + 2 * C_DIM + h * D_HEAD;
    __half* out = g_vT + (size_t)z * D_HEAD * N_SEQ;
    int m0 = blockIdx.x * 32, d0 = blockIdx.y * 32;
    int x = threadIdx.x, y = threadIdx.y;
#pragma unroll
    for (int i = 0; i < 4; i++)
        t[y + i * 8][x] = __half2float(in[(size_t)(m0 + y + i * 8) * QKV_LD + d0 + x]);
    __syncthreads();
#pragma unroll
    for (int i = 0; i < 4; i++)
        out[(size_t)(d0 + y + i * 8) * N_SEQ + m0 + x] = __float2half_rn(t[x][y + i * 8]);
}

// ---------------------------------------------------------------------------
// Fused pre-mix (w_l) -> softmax over m -> post-mix (w_w).
// Reads fp32 g_scores; writes fp16 g_attn. One CTA per (b, n).
// ---------------------------------------------------------------------------
__global__ __launch_bounds__(256) void mixsoftmax_kernel(
    const float* __restrict__ w_l, const float* __restrict__ b_l,
    const float* __restrict__ w_w, const float* __restrict__ b_w)
{
    __shared__ float swl[144], sww[144], sbl[12], sbw[12];
    __shared__ float red[8][12];
    const int tid = threadIdx.x;
    if (tid < 144) { swl[tid] = w_l[tid]; sww[tid] = w_w[tid]; }
    if (tid < 12)  { sbl[tid] = b_l[tid]; sbw[tid] = b_w[tid]; }
    __syncthreads();

    const int bn = blockIdx.x;
    const int b = bn >> 10, n = bn & 1023;
    const size_t base = ((size_t)b * H_HEAD * N_SEQ + n) * N_SEQ;
    const int m0 = tid * 4;
    const int lane = tid & 31, wid = tid >> 5;

    float t[12][4];
#pragma unroll
    for (int g = 0; g < 12; g++) {
        float bl = sbl[g];
        t[g][0] = bl; t[g][1] = bl; t[g][2] = bl; t[g][3] = bl;
    }
#pragma unroll
    for (int h = 0; h < 12; h++) {
        float4 s4 = *reinterpret_cast<const float4*>(g_scores + base + (size_t)h * N_SEQ * N_SEQ + m0);
#pragma unroll
        for (int g = 0; g < 12; g++) {
            float wl = swl[h * 12 + g];
            t[g][0] = fmaf(s4.x, wl, t[g][0]);
            t[g][1] = fmaf(s4.y, wl, t[g][1]);
            t[g][2] = fmaf(s4.z, wl, t[g][2]);
            t[g][3] = fmaf(s4.w, wl, t[g][3]);
        }
    }

    float lmax[12];
#pragma unroll
    for (int g = 0; g < 12; g++) {
        float v = fmaxf(fmaxf(t[g][0], t[g][1]), fmaxf(t[g][2], t[g][3]));
#pragma unroll
        for (int o = 16; o > 0; o >>= 1) v = fmaxf(v, __shfl_xor_sync(0xffffffffu, v, o));
        if (lane == 0) red[wid][g] = v;
    }
    __syncthreads();
#pragma unroll
    for (int g = 0; g < 12; g++) {
        float v = red[0][g];
#pragma unroll
        for (int w = 1; w < 8; w++) v = fmaxf(v, red[w][g]);
        lmax[g] = v;
    }
    __syncthreads();

    float lsum[12];
#pragma unroll
    for (int g = 0; g < 12; g++) {
        t[g][0] = __expf(t[g][0] - lmax[g]);
        t[g][1] = __expf(t[g][1] - lmax[g]);
        t[g][2] = __expf(t[g][2] - lmax[g]);
        t[g][3] = __expf(t[g][3] - lmax[g]);
        float v = (t[g][0] + t[g][1]) + (t[g][2] + t[g][3]);
#pragma unroll
        for (int o = 16; o > 0; o >>= 1) v += __shfl_xor_sync(0xffffffffu, v, o);
        if (lane == 0) red[wid][g] = v;
    }
    __syncthreads();
#pragma unroll
    for (int g = 0; g < 12; g++) {
        float v = red[0][g];
#pragma unroll
        for (int w = 1; w < 8; w++) v += red[w][g];
        lsum[g] = 1.0f / v;
    }

#pragma unroll
    for (int g = 0; g < 12; g++) {
        t[g][0] *= lsum[g]; t[g][1] *= lsum[g]; t[g][2] *= lsum[g]; t[g][3] *= lsum[g];
    }

#pragma unroll
    for (int g = 0; g < 12; g++) {
        float o0 = sbw[g], o1 = sbw[g], o2 = sbw[g], o3 = sbw[g];
#pragma unroll
        for (int h = 0; h < 12; h++) {
            float ww = sww[h * 12 + g];
            o0 = fmaf(t[h][0], ww, o0);
            o1 = fmaf(t[h][1], ww, o1);
            o2 = fmaf(t[h][2], ww, o2);
            o3 = fmaf(t[h][3], ww, o3);
        }
        uint2 p;
        p.x = pack_h2(o0, o1);
        p.y = pack_h2(o2, o3);
        *reinterpret_cast<uint2*>(g_attn + base + (size_t)g * N_SEQ * N_SEQ + m0) = p;
    }
}

// ---------------------------------------------------------------------------
extern "C" void kernel_launch(void* const* d_in, const int* in_sizes, int n_in,
                              void* d_out, int out_size)
{
    const float* x      = (const float*)d_in[0];
    const float* w_qkv  = (const float*)d_in[1];
    const float* b_qkv  = (const float*)d_in[2];
    const float* w_l    = (const float*)d_in[3];
    const float* b_l    = (const float*)d_in[4];
    const float* w_w    = (const float*)d_in[5];
    const float* b_w    = (const float*)d_in[6];
    const float* w_proj = (const float*)d_in[7];
    const float* b_proj = (const float*)d_in[8];
    float* out = (float*)d_out;

    __half *xh_p, *qkv_p, *attn_p, *av_p, *vT_p, *wqkvT_p, *wprojT_p;
    float *scores_p;
    cudaGetSymbolAddress((void**)&xh_p, g_xh);
    cudaGetSymbolAddress((void**)&qkv_p, g_qkv);
    cudaGetSymbolAddress((void**)&scores_p, g_scores);
    cudaGetSymbolAddress((void**)&attn_p, g_attn);
    cudaGetSymbolAddress((void**)&av_p, g_av);
    cudaGetSymbolAddress((void**)&vT_p, g_vT);
    cudaGetSymbolAddress((void**)&wqkvT_p, g_wqkvT);
    cudaGetSymbolAddress((void**)&wprojT_p, g_wprojT);

    // dynamic smem: 3 stages * (128 + BN) rows * 72 halves * 2 bytes
    const int smem128 = 3 * (128 + 128) * 72 * 2;   // 110592 -> 2 CTAs/SM
    const int smem64  = 3 * (128 + 64) * 72 * 2;    // 82944
    cudaFuncSetAttribute(gemm_f16<128, true >, cudaFuncAttributeMaxDynamicSharedMemorySize, smem128);
    cudaFuncSetAttribute(gemm_f16<128, false>, cudaFuncAttributeMaxDynamicSharedMemorySize, smem128);
    cudaFuncSetAttribute(gemm_f16<64,  true >, cudaFuncAttributeMaxDynamicSharedMemorySize, smem64);

    // 0) fp16 conversions: x, transposed weights
    round_x_f16<<<(B_SZ * N_SEQ * C_DIM / 4) / 256, 256>>>(x, xh_p);
    transpose2d<<<dim3(QKV_LD / 32, C_DIM / 32), dim3(32, 8)>>>(w_qkv, wqkvT_p, C_DIM, QKV_LD);
    transpose2d<<<dim3(C_DIM / 32, C_DIM / 32), dim3(32, 8)>>>(w_proj, wprojT_p, C_DIM, C_DIM);

    const long long QB = (long long)N_SEQ * QKV_LD;
    const long long SH = (long long)N_SEQ * N_SEQ;
    const long long VH = (long long)D_HEAD * N_SEQ;

    // 1) QKV projection: [8192,768] @ wqkvT^T + bias -> fp16 qkv
    gemm_f16<128, true><<<dim3(QKV_LD / 128, B_SZ * N_SEQ / 128, 1), 256, smem128>>>(
        xh_p, wqkvT_p, b_qkv, qkv_p, C_DIM, C_DIM, C_DIM, QKV_LD,
        0, 0, 0, 0, 0, 0, 1.0f);

    // 2) transpose V slices into g_vT[z][d][m]
    transpose_v<<<dim3(N_SEQ / 32, D_HEAD / 32, B_SZ * H_HEAD), dim3(32, 8)>>>();

    // 3) scores = SCALE * q @ k^T per (b,h) -> raw fp32 (full batch, z=96)
    gemm_f16<128, false><<<dim3(N_SEQ / 128, N_SEQ / 128, B_SZ * H_HEAD), 256, smem128>>>(
        qkv_p, qkv_p + C_DIM, nullptr, scores_p, D_HEAD, QKV_LD, QKV_LD, N_SEQ,
        QB, D_HEAD, QB, D_HEAD, H_HEAD * SH, SH, SCALE);

    // 4) fused talking-heads pre-mix + softmax + post-mix -> fp16 attn
    mixsoftmax_kernel<<<B_SZ * N_SEQ, 256>>>(w_l, b_l, w_w, b_w);

    // 5) av = attn @ vT^T -> fp16 av (full batch, z=96)
    gemm_f16<64, true><<<dim3(1, N_SEQ / 128, B_SZ * H_HEAD), 256, smem64>>>(
        attn_p, vT_p, nullptr, av_p, N_SEQ, N_SEQ, N_SEQ, C_DIM,
        H_HEAD * SH, SH, H_HEAD * VH, VH, (long long)N_SEQ * C_DIM, D_HEAD, 1.0f);

    // 6) out = av @ wprojT^T + bias (fp32 out)
    gemm_f16<128, false><<<dim3(C_DIM / 128, B_SZ * N_SEQ / 128, 1), 256, smem128>>>(
        av_p, wprojT_p, b_proj, out, C_DIM, C_DIM, C_DIM, C_DIM,
        0, 0, 0, 0, 0, 0, 1.0f);
}

// round 14
// speedup vs baseline: 1.1527x; 1.0026x over previous
#include <cuda_runtime.h>
#include <cuda_fp16.h>
#include <math.h>
#include <stdint.h>

// Problem constants
#define B_SZ   8
#define N_SEQ  1024
#define C_DIM  768
#define H_HEAD 12
#define D_HEAD 64
#define QKV_LD 2304            // 3*C
#define SCALE  0.125f          // 64^-0.5

// Scratch (allocation-free: __device__ globals). GEMM operands fp16, acc fp32.
// g_scores buffer reused as fp16 (half the bytes) — scores now stored fp16.
__device__ __half g_xh[(size_t)B_SZ * N_SEQ * C_DIM];
__device__ __half g_qkv[(size_t)B_SZ * N_SEQ * 3 * C_DIM];            // [8192, 2304]
__device__ float  g_scores[(size_t)B_SZ * H_HEAD * N_SEQ * N_SEQ];    // reinterpreted as half
__device__ __half g_attn[(size_t)B_SZ * H_HEAD * N_SEQ * N_SEQ];      // [96,1024,1024] fp16
__device__ __half g_av[(size_t)B_SZ * N_SEQ * C_DIM];                 // [8192, 768]
__device__ __half g_vT[(size_t)B_SZ * H_HEAD * D_HEAD * N_SEQ];       // [96, 64, 1024]
__device__ __half g_wqkvT[(size_t)3 * C_DIM * C_DIM];                 // [2304, 768]
__device__ __half g_wprojT[(size_t)C_DIM * C_DIM];                    // [768, 768]

// ---------------------------------------------------------------------------
// helpers
// ---------------------------------------------------------------------------
__device__ __forceinline__ void cpa16(unsigned s, const void* g) {
    asm volatile("cp.async.cg.shared.global [%0], [%1], 16;" :: "r"(s), "l"(g));
}
#define CPA_COMMIT() asm volatile("cp.async.commit_group;")
#define CPA_WAIT(n)  asm volatile("cp.async.wait_group %0;" :: "n"(n))

__device__ __forceinline__ uint32_t pack_h2(float a, float b) {
    __half2 h = __floats2half2_rn(a, b);
    return *reinterpret_cast<uint32_t*>(&h);
}

#define MMA_F16(d, a, b)                                                      \
    asm volatile(                                                             \
        "mma.sync.aligned.m16n8k16.row.col.f32.f16.f16.f32 "                  \
        "{%0,%1,%2,%3}, {%4,%5,%6,%7}, {%8,%9}, {%0,%1,%2,%3};"               \
        : "+f"(d[0]), "+f"(d[1]), "+f"(d[2]), "+f"(d[3])                      \
        : "r"(a[0]), "r"(a[1]), "r"(a[2]), "r"(a[3]), "r"(b[0]), "r"(b[1]))

#define LDSM4(r0, r1, r2, r3, addr)                                           \
    asm volatile(                                                             \
        "ldmatrix.sync.aligned.m8n8.x4.shared.b16 {%0,%1,%2,%3}, [%4];"       \
        : "=r"(r0), "=r"(r1), "=r"(r2), "=r"(r3) : "r"(addr))

// ---------------------------------------------------------------------------
// fp16 NT GEMM: C[M,N] = scale * (A[M,K] @ B[N,K]^T) + bias[N]
// BM=128, BK=64, 256 threads (8 warps 4x2), warp tile 32 x (BN/2),
// mma m16n8k16 (fp16 in, fp32 acc), 3-stage cp.async (2 chunks in flight),
// ldmatrix.x4 fragment loads (conflict-free on pad-72 rows: stride 36 words).
// 96+ regs / 2 CTAs/SM. OUT_HALF: C stored as __half else fp32.
// ---------------------------------------------------------------------------
template<int BN, bool OUT_HALF>
__global__ __launch_bounds__(256) void gemm_f16(
    const __half* __restrict__ Ag, const __half* __restrict__ Bg,
    const float* __restrict__ bias, void* __restrict__ Cg,
    int K, int lda, int ldb, int ldc,
    long long az1, long long az2, long long bz1, long long bz2,
    long long cz1, long long cz2, float scale)
{
    constexpr int WN = BN / 2;
    constexpr int NI = WN / 8;
    constexpr int NP = NI / 2;            // B ldmatrix pairs
    constexpr int LROW = 72;              // 64 halves + 8 pad
    constexpr int ASTG = 128 * LROW;      // halves per A stage
    constexpr int BSTG = BN * LROW;
    constexpr int NSTG = 3;

    extern __shared__ __half sh[];
    const uint32_t sb = (uint32_t)__cvta_generic_to_shared(sh);
    const uint32_t sbB = sb + NSTG * ASTG * 2;

    const int tid = threadIdx.x;
    const int lane = tid & 31, warp = tid >> 5;
    const int wm = warp & 3, wn = warp >> 2;
    const int g = lane >> 2, tg = lane & 3;

    const int z = blockIdx.z;
    const int zb = z / H_HEAD, zh = z % H_HEAD;
    const __half* A = Ag + zb * az1 + zh * az2 + (size_t)blockIdx.y * 128 * lda;
    const __half* B = Bg + zb * bz1 + zh * bz2 + (size_t)blockIdx.x * BN * ldb;

    const int lr = tid >> 2;              // load row within 64-row group
    const int lc = (tid & 3) * 16;        // load col (halves), 2 chunks: lc, lc+8

    uint32_t aOff[2];
#pragma unroll
    for (int mi = 0; mi < 2; mi++)
        aOff[mi] = ((wm * 32 + mi * 16 + (lane & 15)) * LROW + (lane >> 4) * 8) * 2;
    uint32_t bOff[NP];
#pragma unroll
    for (int p = 0; p < NP; p++)
        bOff[p] = ((wn * WN + p * 16 + (lane & 7) + ((lane >> 4) & 1) * 8) * LROW +
                   ((lane >> 3) & 1) * 8) * 2;

    float acc[2][NI][4];
#pragma unroll
    for (int mi = 0; mi < 2; mi++)
#pragma unroll
        for (int ni = 0; ni < NI; ni++)
#pragma unroll
            for (int j = 0; j < 4; j++) acc[mi][ni][j] = 0.f;

    const int niter = K >> 6;             // BK = 64

    auto stage_load = [&](int st, int k0) {
#pragma unroll
        for (int l = 0; l < 2; l++) {     // A: 128 rows in 2 groups of 64
            int r = lr + l * 64;
            cpa16(sb + (st * ASTG + r * LROW + lc) * 2,      A + (size_t)r * lda + k0 + lc);
            cpa16(sb + (st * ASTG + r * LROW + lc + 8) * 2,  A + (size_t)r * lda + k0 + lc + 8);
        }
#pragma unroll
        for (int l = 0; l < BN / 64; l++) {
            int r = lr + l * 64;
            cpa16(sbB + (st * BSTG + r * LROW + lc) * 2,     B + (size_t)r * ldb + k0 + lc);
            cpa16(sbB + (st * BSTG + r * LROW + lc + 8) * 2, B + (size_t)r * ldb + k0 + lc + 8);
        }
        CPA_COMMIT();
    };

    stage_load(0, 0);
    if (niter > 1) stage_load(1, 64);

    int st = 0;
    for (int i = 0; i < niter; i++) {
        // commits = min(2+i, niter); chunk i complete iff pending <=
        // min(1, niter-i-1). Tail drains fully (proven R6 ladder).
        if (i + 1 < niter) { CPA_WAIT(1); } else { CPA_WAIT(0); }
        __syncthreads();
        int nld = i + 2;
        if (nld < niter) {
            int ls = nld - (nld / 3) * 3;
            stage_load(ls, nld << 6);
        }

        const uint32_t aS = sb + st * ASTG * 2;
        const uint32_t bS = sbB + st * BSTG * 2;
#pragma unroll
        for (int kk = 0; kk < 4; kk++) {               // four 16-k groups, +32B each
            unsigned a[2][4], b[NI][2];
#pragma unroll
            for (int mi = 0; mi < 2; mi++)
                LDSM4(a[mi][0], a[mi][1], a[mi][2], a[mi][3],
                      aS + aOff[mi] + kk * 32);
#pragma unroll
            for (int p = 0; p < NP; p++)
                LDSM4(b[2 * p][0], b[2 * p][1], b[2 * p + 1][0], b[2 * p + 1][1],
                      bS + bOff[p] + kk * 32);
#pragma unroll
            for (int mi = 0; mi < 2; mi++)
#pragma unroll
                for (int ni = 0; ni < NI; ni++)
                    MMA_F16(acc[mi][ni], a[mi], b[ni]);
        }
        st++; if (st == 3) st = 0;
    }

    // epilogue
    const int row_base = blockIdx.y * 128 + wm * 32;
    const int col_base = blockIdx.x * BN + wn * WN;
#pragma unroll
    for (int mi = 0; mi < 2; mi++) {
#pragma unroll
        for (int ni = 0; ni < NI; ni++) {
            int r0 = row_base + mi * 16 + g;
            int c = col_base + ni * 8 + 2 * tg;
            float b0 = 0.f, b1 = 0.f;
            if (bias) { b0 = bias[c]; b1 = bias[c + 1]; }
            float e00 = acc[mi][ni][0] * scale + b0;
            float e01 = acc[mi][ni][1] * scale + b1;
            float e10 = acc[mi][ni][2] * scale + b0;
            float e11 = acc[mi][ni][3] * scale + b1;
            if (OUT_HALF) {
                __half* C = (__half*)Cg + zb * cz1 + zh * cz2;
                *reinterpret_cast<uint32_t*>(C + (size_t)r0 * ldc + c) = pack_h2(e00, e01);
                *reinterpret_cast<uint32_t*>(C + (size_t)(r0 + 8) * ldc + c) = pack_h2(e10, e11);
            } else {
                float* C = (float*)Cg + zb * cz1 + zh * cz2;
                *reinterpret_cast<float2*>(C + (size_t)r0 * ldc + c) = make_float2(e00, e01);
                *reinterpret_cast<float2*>(C + (size_t)(r0 + 8) * ldc + c) = make_float2(e10, e11);
            }
        }
    }
}

// ---------------------------------------------------------------------------
// elementwise fp16 round of x
// ---------------------------------------------------------------------------
__global__ void round_x_f16(const float* __restrict__ in, __half* __restrict__ out)
{
    int i = blockIdx.x * 256 + threadIdx.x;
    float4 v = reinterpret_cast<const float4*>(in)[i];
    uint2 p;
    p.x = pack_h2(v.x, v.y);
    p.y = pack_h2(v.z, v.w);
    reinterpret_cast<uint2*>(out)[i] = p;
}

// ---------------------------------------------------------------------------
// 32x32 tiled transpose fp32 -> fp16
// ---------------------------------------------------------------------------
__global__ void transpose2d(const float* __restrict__ in, __half* __restrict__ out,
                            int R, int Cc)
{
    __shared__ float t[32][33];
    int c0 = blockIdx.x * 32, r0 = blockIdx.y * 32;
    int x = threadIdx.x, y = threadIdx.y;
#pragma unroll
    for (int i = 0; i < 4; i++)
        t[y + i * 8][x] = in[(size_t)(r0 + y + i * 8) * Cc + c0 + x];
    __syncthreads();
#pragma unroll
    for (int i = 0; i < 4; i++)
        out[(size_t)(c0 + y + i * 8) * R + r0 + x] = __float2half_rn(t[x][y + i * 8]);
}

// V slice of g_qkv (half) -> g_vT[z][d][m] (half)
__global__ void transpose_v()
{
    __shared__ float t[32][33];
    int z = blockIdx.z;
    int b = z / H_HEAD, h = z % H_HEAD;
    const __half* in = g_qkv + (size_t)b * N_SEQ * QKV_LD + 2 * C_DIM + h * D_HEAD;
    __half* out = g_vT + (size_t)z * D_HEAD * N_SEQ;
    int m0 = blockIdx.x * 32, d0 = blockIdx.y * 32;
    int x = threadIdx.x, y = threadIdx.y;
#pragma unroll
    for (int i = 0; i < 4; i++)
        t[y + i * 8][x] = __half2float(in[(size_t)(m0 + y + i * 8) * QKV_LD + d0 + x]);
    __syncthreads();
#pragma unroll
    for (int i = 0; i < 4; i++)
        out[(size_t)(d0 + y + i * 8) * N_SEQ + m0 + x] = __float2half_rn(t[x][y + i * 8]);
}

// ---------------------------------------------------------------------------
// Fused pre-mix (w_l) -> softmax over m -> post-mix (w_w).
// Reads fp16 scores (g_scores reinterpreted); writes fp16 g_attn.
// One CTA per (b, n).
// ---------------------------------------------------------------------------
__global__ __launch_bounds__(256) void mixsoftmax_kernel(
    const float* __restrict__ w_l, const float* __restrict__ b_l,
    const float* __restrict__ w_w, const float* __restrict__ b_w)
{
    __shared__ float swl[144], sww[144], sbl[12], sbw[12];
    __shared__ float red[8][12];
    const int tid = threadIdx.x;
    if (tid < 144) { swl[tid] = w_l[tid]; sww[tid] = w_w[tid]; }
    if (tid < 12)  { sbl[tid] = b_l[tid]; sbw[tid] = b_w[tid]; }
    __syncthreads();

    const __half* sp = reinterpret_cast<const __half*>(g_scores);
    const int bn = blockIdx.x;
    const int b = bn >> 10, n = bn & 1023;
    const size_t base = ((size_t)b * H_HEAD * N_SEQ + n) * N_SEQ;
    const int m0 = tid * 4;
    const int lane = tid & 31, wid = tid >> 5;

    float t[12][4];
#pragma unroll
    for (int g = 0; g < 12; g++) {
        float bl = sbl[g];
        t[g][0] = bl; t[g][1] = bl; t[g][2] = bl; t[g][3] = bl;
    }
#pragma unroll
    for (int h = 0; h < 12; h++) {
        uint2 u = *reinterpret_cast<const uint2*>(sp + base + (size_t)h * N_SEQ * N_SEQ + m0);
        float2 f01 = __half22float2(*reinterpret_cast<const __half2*>(&u.x));
        float2 f23 = __half22float2(*reinterpret_cast<const __half2*>(&u.y));
#pragma unroll
        for (int g = 0; g < 12; g++) {
            float wl = swl[h * 12 + g];
            t[g][0] = fmaf(f01.x, wl, t[g][0]);
            t[g][1] = fmaf(f01.y, wl, t[g][1]);
            t[g][2] = fmaf(f23.x, wl, t[g][2]);
            t[g][3] = fmaf(f23.y, wl, t[g][3]);
        }
    }

    float lmax[12];
#pragma unroll
    for (int g = 0; g < 12; g++) {
        float v = fmaxf(fmaxf(t[g][0], t[g][1]), fmaxf(t[g][2], t[g][3]));
#pragma unroll
        for (int o = 16; o > 0; o >>= 1) v = fmaxf(v, __shfl_xor_sync(0xffffffffu, v, o));
        if (lane == 0) red[wid][g] = v;
    }
    __syncthreads();
#pragma unroll
    for (int g = 0; g < 12; g++) {
        float v = red[0][g];
#pragma unroll
        for (int w = 1; w < 8; w++) v = fmaxf(v, red[w][g]);
        lmax[g] = v;
    }
    __syncthreads();

    float lsum[12];
#pragma unroll
    for (int g = 0; g < 12; g++) {
        t[g][0] = __expf(t[g][0] - lmax[g]);
        t[g][1] = __expf(t[g][1] - lmax[g]);
        t[g][2] = __expf(t[g][2] - lmax[g]);
        t[g][3] = __expf(t[g][3] - lmax[g]);
        float v = (t[g][0] + t[g][1]) + (t[g][2] + t[g][3]);
#pragma unroll
        for (int o = 16; o > 0; o >>= 1) v += __shfl_xor_sync(0xffffffffu, v, o);
        if (lane == 0) red[wid][g] = v;
    }
    __syncthreads();
#pragma unroll
    for (int g = 0; g < 12; g++) {
        float v = red[0][g];
#pragma unroll
        for (int w = 1; w < 8; w++) v += red[w][g];
        lsum[g] = 1.0f / v;
    }

#pragma unroll
    for (int g = 0; g < 12; g++) {
        t[g][0] *= lsum[g]; t[g][1] *= lsum[g]; t[g][2] *= lsum[g]; t[g][3] *= lsum[g];
    }

#pragma unroll
    for (int g = 0; g < 12; g++) {
        float o0 = sbw[g], o1 = sbw[g], o2 = sbw[g], o3 = sbw[g];
#pragma unroll
        for (int h = 0; h < 12; h++) {
            float ww = sww[h * 12 + g];
            o0 = fmaf(t[h][0], ww, o0);
            o1 = fmaf(t[h][1], ww, o1);
            o2 = fmaf(t[h][2], ww, o2);
            o3 = fmaf(t[h][3], ww, o3);
        }
        uint2 p;
        p.x = pack_h2(o0, o1);
        p.y = pack_h2(o2, o3);
        *reinterpret_cast<uint2*>(g_attn + base + (size_t)g * N_SEQ * N_SEQ + m0) = p;
    }
}

// ---------------------------------------------------------------------------
extern "C" void kernel_launch(void* const* d_in, const int* in_sizes, int n_in,
                              void* d_out, int out_size)
{
    const float* x      = (const float*)d_in[0];
    const float* w_qkv  = (const float*)d_in[1];
    const float* b_qkv  = (const float*)d_in[2];
    const float* w_l    = (const float*)d_in[3];
    const float* b_l    = (const float*)d_in[4];
    const float* w_w    = (const float*)d_in[5];
    const float* b_w    = (const float*)d_in[6];
    const float* w_proj = (const float*)d_in[7];
    const float* b_proj = (const float*)d_in[8];
    float* out = (float*)d_out;

    __half *xh_p, *qkv_p, *attn_p, *av_p, *vT_p, *wqkvT_p, *wprojT_p;
    float *scores_p;
    cudaGetSymbolAddress((void**)&xh_p, g_xh);
    cudaGetSymbolAddress((void**)&qkv_p, g_qkv);
    cudaGetSymbolAddress((void**)&scores_p, g_scores);
    cudaGetSymbolAddress((void**)&attn_p, g_attn);
    cudaGetSymbolAddress((void**)&av_p, g_av);
    cudaGetSymbolAddress((void**)&vT_p, g_vT);
    cudaGetSymbolAddress((void**)&wqkvT_p, g_wqkvT);
    cudaGetSymbolAddress((void**)&wprojT_p, g_wprojT);
    __half* scores_h = reinterpret_cast<__half*>(scores_p);   // fp16 scores view

    // dynamic smem: 3 stages * (128 + BN) rows * 72 halves * 2 bytes
    const int smem128 = 3 * (128 + 128) * 72 * 2;   // 110592 -> 2 CTAs/SM
    const int smem64  = 3 * (128 + 64) * 72 * 2;    // 82944
    cudaFuncSetAttribute(gemm_f16<128, true >, cudaFuncAttributeMaxDynamicSharedMemorySize, smem128);
    cudaFuncSetAttribute(gemm_f16<128, false>, cudaFuncAttributeMaxDynamicSharedMemorySize, smem128);
    cudaFuncSetAttribute(gemm_f16<64,  true >, cudaFuncAttributeMaxDynamicSharedMemorySize, smem64);

    // 0) fp16 conversions: x, transposed weights
    round_x_f16<<<(B_SZ * N_SEQ * C_DIM / 4) / 256, 256>>>(x, xh_p);
    transpose2d<<<dim3(QKV_LD / 32, C_DIM / 32), dim3(32, 8)>>>(w_qkv, wqkvT_p, C_DIM, QKV_LD);
    transpose2d<<<dim3(C_DIM / 32, C_DIM / 32), dim3(32, 8)>>>(w_proj, wprojT_p, C_DIM, C_DIM);

    const long long QB = (long long)N_SEQ * QKV_LD;
    const long long SH = (long long)N_SEQ * N_SEQ;
    const long long VH = (long long)D_HEAD * N_SEQ;

    // 1) QKV projection: [8192,768] @ wqkvT^T + bias -> fp16 qkv
    gemm_f16<128, true><<<dim3(QKV_LD / 128, B_SZ * N_SEQ / 128, 1), 256, smem128>>>(
        xh_p, wqkvT_p, b_qkv, qkv_p, C_DIM, C_DIM, C_DIM, QKV_LD,
        0, 0, 0, 0, 0, 0, 1.0f);

    // 2) transpose V slices into g_vT[z][d][m]
    transpose_v<<<dim3(N_SEQ / 32, D_HEAD / 32, B_SZ * H_HEAD), dim3(32, 8)>>>();

    // 3) scores = SCALE * q @ k^T per (b,h) -> fp16 (full batch, z=96)
    gemm_f16<128, true><<<dim3(N_SEQ / 128, N_SEQ / 128, B_SZ * H_HEAD), 256, smem128>>>(
        qkv_p, qkv_p + C_DIM, nullptr, scores_h, D_HEAD, QKV_LD, QKV_LD, N_SEQ,
        QB, D_HEAD, QB, D_HEAD, H_HEAD * SH, SH, SCALE);

    // 4) fused talking-heads pre-mix + softmax + post-mix -> fp16 attn
    mixsoftmax_kernel<<<B_SZ * N_SEQ, 256>>>(w_l, b_l, w_w, b_w);

    // 5) av = attn @ vT^T -> fp16 av (full batch, z=96)
    gemm_f16<64, true><<<dim3(1, N_SEQ / 128, B_SZ * H_HEAD), 256, smem64>>>(
        attn_p, vT_p, nullptr, av_p, N_SEQ, N_SEQ, N_SEQ, C_DIM,
        H_HEAD * SH, SH, H_HEAD * VH, VH, (long long)N_SEQ * C_DIM, D_HEAD, 1.0f);

    // 6) out = av @ wprojT^T + bias (fp32 out)
    gemm_f16<128, false><<<dim3(C_DIM / 128, B_SZ * N_SEQ / 128, 1), 256, smem128>>>(
        av_p, wprojT_p, b_proj, out, C_DIM, C_DIM, C_DIM, C_DIM,
        0, 0, 0, 0, 0, 0, 1.0f);
}

// round 17
// speedup vs baseline: 1.1598x; 1.0062x over previous
#include <cuda_runtime.h>
#include <cuda_fp16.h>
#include <math.h>
#include <stdint.h>

// Problem constants
#define B_SZ   8
#define N_SEQ  1024
#define C_DIM  768
#define H_HEAD 12
#define D_HEAD 64
#define QKV_LD 2304            // 3*C
#define SCALE  0.125f          // 64^-0.5

// Scratch (allocation-free: __device__ globals). GEMM operands fp16, acc fp32.
__device__ __half g_xh[(size_t)B_SZ * N_SEQ * C_DIM];
__device__ __half g_qkv[(size_t)B_SZ * N_SEQ * 3 * C_DIM];            // [8192, 2304]
__device__ float  g_scores[(size_t)B_SZ * H_HEAD * N_SEQ * N_SEQ];    // reinterpreted as half
__device__ __half g_attn[(size_t)B_SZ * H_HEAD * N_SEQ * N_SEQ];      // [96,1024,1024] fp16
__device__ __half g_av[(size_t)B_SZ * N_SEQ * C_DIM];                 // [8192, 768]
__device__ __half g_vT[(size_t)B_SZ * H_HEAD * D_HEAD * N_SEQ];       // [96, 64, 1024]
__device__ __half g_wqkvT[(size_t)3 * C_DIM * C_DIM];                 // [2304, 768]
__device__ __half g_wprojT[(size_t)C_DIM * C_DIM];                    // [768, 768]

// ---------------------------------------------------------------------------
// helpers
// ---------------------------------------------------------------------------
__device__ __forceinline__ void cpa16(unsigned s, const void* g) {
    asm volatile("cp.async.cg.shared.global [%0], [%1], 16;" :: "r"(s), "l"(g));
}
#define CPA_COMMIT() asm volatile("cp.async.commit_group;")
#define CPA_WAIT(n)  asm volatile("cp.async.wait_group %0;" :: "n"(n))

__device__ __forceinline__ uint32_t pack_h2(float a, float b) {
    __half2 h = __floats2half2_rn(a, b);
    return *reinterpret_cast<uint32_t*>(&h);
}

#define MMA_F16(d, a, b)                                                      \
    asm volatile(                                                             \
        "mma.sync.aligned.m16n8k16.row.col.f32.f16.f16.f32 "                  \
        "{%0,%1,%2,%3}, {%4,%5,%6,%7}, {%8,%9}, {%0,%1,%2,%3};"               \
        : "+f"(d[0]), "+f"(d[1]), "+f"(d[2]), "+f"(d[3])                      \
        : "r"(a[0]), "r"(a[1]), "r"(a[2]), "r"(a[3]), "r"(b[0]), "r"(b[1]))

#define LDSM4(r0, r1, r2, r3, addr)                                           \
    asm volatile(                                                             \
        "ldmatrix.sync.aligned.m8n8.x4.shared.b16 {%0,%1,%2,%3}, [%4];"       \
        : "=r"(r0), "=r"(r1), "=r"(r2), "=r"(r3) : "r"(addr))

// ---------------------------------------------------------------------------
// fp16 NT GEMM: C[M,N] = scale * (A[M,K] @ B[N,K]^T) + bias[N]
// BM=128, BK=64, 256 threads (8 warps 4x2), warp tile 32 x (BN/2),
// mma m16n8k16 (fp16 in, fp32 acc), 3-stage cp.async (2 chunks in flight),
// ldmatrix.x4 fragment loads (conflict-free on pad-72 rows).
// OUT_HALF: C stored as __half else fp32.
// ---------------------------------------------------------------------------
template<int BN, bool OUT_HALF>
__global__ __launch_bounds__(256) void gemm_f16(
    const __half* __restrict__ Ag, const __half* __restrict__ Bg,
    const float* __restrict__ bias, void* __restrict__ Cg,
    int K, int lda, int ldb, int ldc,
    long long az1, long long az2, long long bz1, long long bz2,
    long long cz1, long long cz2, float scale)
{
    constexpr int WN = BN / 2;
    constexpr int NI = WN / 8;
    constexpr int NP = NI / 2;
    constexpr int LROW = 72;
    constexpr int ASTG = 128 * LROW;
    constexpr int BSTG = BN * LROW;
    constexpr int NSTG = 3;

    extern __shared__ __half sh[];
    const uint32_t sb = (uint32_t)__cvta_generic_to_shared(sh);
    const uint32_t sbB = sb + NSTG * ASTG * 2;

    const int tid = threadIdx.x;
    const int lane = tid & 31, warp = tid >> 5;
    const int wm = warp & 3, wn = warp >> 2;
    const int g = lane >> 2, tg = lane & 3;

    const int z = blockIdx.z;
    const int zb = z / H_HEAD, zh = z % H_HEAD;
    const __half* A = Ag + zb * az1 + zh * az2 + (size_t)blockIdx.y * 128 * lda;
    const __half* B = Bg + zb * bz1 + zh * bz2 + (size_t)blockIdx.x * BN * ldb;

    const int lr = tid >> 2;
    const int lc = (tid & 3) * 16;

    uint32_t aOff[2];
#pragma unroll
    for (int mi = 0; mi < 2; mi++)
        aOff[mi] = ((wm * 32 + mi * 16 + (lane & 15)) * LROW + (lane >> 4) * 8) * 2;
    uint32_t bOff[NP];
#pragma unroll
    for (int p = 0; p < NP; p++)
        bOff[p] = ((wn * WN + p * 16 + (lane & 7) + ((lane >> 4) & 1) * 8) * LROW +
                   ((lane >> 3) & 1) * 8) * 2;

    float acc[2][NI][4];
#pragma unroll
    for (int mi = 0; mi < 2; mi++)
#pragma unroll
        for (int ni = 0; ni < NI; ni++)
#pragma unroll
            for (int j = 0; j < 4; j++) acc[mi][ni][j] = 0.f;

    const int niter = K >> 6;

    auto stage_load = [&](int st, int k0) {
#pragma unroll
        for (int l = 0; l < 2; l++) {
            int r = lr + l * 64;
            cpa16(sb + (st * ASTG + r * LROW + lc) * 2,      A + (size_t)r * lda + k0 + lc);
            cpa16(sb + (st * ASTG + r * LROW + lc + 8) * 2,  A + (size_t)r * lda + k0 + lc + 8);
        }
#pragma unroll
        for (int l = 0; l < BN / 64; l++) {
            int r = lr + l * 64;
            cpa16(sbB + (st * BSTG + r * LROW + lc) * 2,     B + (size_t)r * ldb + k0 + lc);
            cpa16(sbB + (st * BSTG + r * LROW + lc + 8) * 2, B + (size_t)r * ldb + k0 + lc + 8);
        }
        CPA_COMMIT();
    };

    stage_load(0, 0);
    if (niter > 1) stage_load(1, 64);

    int st = 0;
    for (int i = 0; i < niter; i++) {
        if (i + 1 < niter) { CPA_WAIT(1); } else { CPA_WAIT(0); }
        __syncthreads();
        int nld = i + 2;
        if (nld < niter) {
            int ls = nld - (nld / 3) * 3;
            stage_load(ls, nld << 6);
        }

        const uint32_t aS = sb + st * ASTG * 2;
        const uint32_t bS = sbB + st * BSTG * 2;
#pragma unroll
        for (int kk = 0; kk < 4; kk++) {
            unsigned a[2][4], b[NI][2];
#pragma unroll
            for (int mi = 0; mi < 2; mi++)
                LDSM4(a[mi][0], a[mi][1], a[mi][2], a[mi][3],
                      aS + aOff[mi] + kk * 32);
#pragma unroll
            for (int p = 0; p < NP; p++)
                LDSM4(b[2 * p][0], b[2 * p][1], b[2 * p + 1][0], b[2 * p + 1][1],
                      bS + bOff[p] + kk * 32);
#pragma unroll
            for (int mi = 0; mi < 2; mi++)
#pragma unroll
                for (int ni = 0; ni < NI; ni++)
                    MMA_F16(acc[mi][ni], a[mi], b[ni]);
        }
        st++; if (st == 3) st = 0;
    }

    const int row_base = blockIdx.y * 128 + wm * 32;
    const int col_base = blockIdx.x * BN + wn * WN;
#pragma unroll
    for (int mi = 0; mi < 2; mi++) {
#pragma unroll
        for (int ni = 0; ni < NI; ni++) {
            int r0 = row_base + mi * 16 + g;
            int c = col_base + ni * 8 + 2 * tg;
            float b0 = 0.f, b1 = 0.f;
            if (bias) { b0 = bias[c]; b1 = bias[c + 1]; }
            float e00 = acc[mi][ni][0] * scale + b0;
            float e01 = acc[mi][ni][1] * scale + b1;
            float e10 = acc[mi][ni][2] * scale + b0;
            float e11 = acc[mi][ni][3] * scale + b1;
            if (OUT_HALF) {
                __half* C = (__half*)Cg + zb * cz1 + zh * cz2;
                *reinterpret_cast<uint32_t*>(C + (size_t)r0 * ldc + c) = pack_h2(e00, e01);
                *reinterpret_cast<uint32_t*>(C + (size_t)(r0 + 8) * ldc + c) = pack_h2(e10, e11);
            } else {
                float* C = (float*)Cg + zb * cz1 + zh * cz2;
                *reinterpret_cast<float2*>(C + (size_t)r0 * ldc + c) = make_float2(e00, e01);
                *reinterpret_cast<float2*>(C + (size_t)(r0 + 8) * ldc + c) = make_float2(e10, e11);
            }
        }
    }
}

// ---------------------------------------------------------------------------
// Dedicated QK kernel: q loaded ONCE and fully drained (WAIT(0) + barrier)
// before the k pipeline starts; k uses the proven homogeneous 3-stage ladder.
// A fragments re-read from static q smem each m-iter (proven LDSM pattern).
// FIX vs R15/R16: the n-tile row offset was applied BOTH in the C base pointer
// and in row_base (double-counted). C now carries only the z offset.
// ---------------------------------------------------------------------------
__global__ __launch_bounds__(256) void qk_kernel()
{
    constexpr int LROW = 72;
    constexpr int QSTG = 128 * LROW;      // q halves
    constexpr int KSTG = 64 * LROW;       // k stage halves (BN=64)
    constexpr int MI_N = 16;              // 1024 / 64 m-iters

    extern __shared__ __half sh[];
    const uint32_t sb = (uint32_t)__cvta_generic_to_shared(sh);
    const uint32_t sbK = sb + QSTG * 2;

    const int tid = threadIdx.x;
    const int lane = tid & 31, warp = tid >> 5;
    const int wm = warp & 3, wn = warp >> 2;
    const int g = lane >> 2, tg = lane & 3;

    const int z = blockIdx.z;
    const int zb = z / H_HEAD, zh = z % H_HEAD;
    const long long QB = (long long)N_SEQ * QKV_LD;
    const __half* Q = g_qkv + zb * QB + zh * D_HEAD + (size_t)blockIdx.x * 128 * QKV_LD;
    const __half* Kt = g_qkv + zb * QB + C_DIM + zh * D_HEAD;
    __half* C = reinterpret_cast<__half*>(g_scores) + (size_t)z * N_SEQ * N_SEQ;

    const int lr = tid >> 2;              // 0..63
    const int lc = (tid & 3) * 16;

    // ---- q tile: load, drain fully, barrier. No q group outlives this. ----
#pragma unroll
    for (int l = 0; l < 2; l++) {
        int r = lr + l * 64;
        cpa16(sb + (r * LROW + lc) * 2,     Q + (size_t)r * QKV_LD + lc);
        cpa16(sb + (r * LROW + lc + 8) * 2, Q + (size_t)r * QKV_LD + lc + 8);
    }
    CPA_COMMIT();
    CPA_WAIT(0);
    __syncthreads();

    // ---- k pipeline: proven homogeneous 3-stage ladder ----
    auto kload = [&](int st, int m0) {
        int r = lr;                        // 64 rows, 4 threads per row
        cpa16(sbK + (st * KSTG + r * LROW + lc) * 2,
              Kt + (size_t)(m0 + r) * QKV_LD + lc);
        cpa16(sbK + (st * KSTG + r * LROW + lc + 8) * 2,
              Kt + (size_t)(m0 + r) * QKV_LD + lc + 8);
        CPA_COMMIT();
    };

    kload(0, 0);
    kload(1, 64);

    uint32_t aOff[2];
#pragma unroll
    for (int mi = 0; mi < 2; mi++)
        aOff[mi] = ((wm * 32 + mi * 16 + (lane & 15)) * LROW + (lane >> 4) * 8) * 2;
    uint32_t bOff[2];
#pragma unroll
    for (int p = 0; p < 2; p++)
        bOff[p] = ((wn * 32 + p * 16 + (lane & 7) + ((lane >> 4) & 1) * 8) * LROW +
                   ((lane >> 3) & 1) * 8) * 2;

    const int row_base = blockIdx.x * 128 + wm * 32;   // global n row (sole offset)

    int st = 0;
    for (int i = 0; i < MI_N; i++) {
        if (i + 1 < MI_N) { CPA_WAIT(1); } else { CPA_WAIT(0); }
        __syncthreads();
        int nld = i + 2;
        if (nld < MI_N) {
            int ls = nld - (nld / 3) * 3;
            kload(ls, nld * 64);
        }

        const uint32_t bS = sbK + st * KSTG * 2;
        float acc[2][4][4];
#pragma unroll
        for (int mi = 0; mi < 2; mi++)
#pragma unroll
            for (int ni = 0; ni < 4; ni++)
#pragma unroll
                for (int j = 0; j < 4; j++) acc[mi][ni][j] = 0.f;

#pragma unroll
        for (int kk = 0; kk < 4; kk++) {
            unsigned a[2][4], b[4][2];
#pragma unroll
            for (int mi = 0; mi < 2; mi++)
                LDSM4(a[mi][0], a[mi][1], a[mi][2], a[mi][3],
                      sb + aOff[mi] + kk * 32);
#pragma unroll
            for (int p = 0; p < 2; p++)
                LDSM4(b[2 * p][0], b[2 * p][1], b[2 * p + 1][0], b[2 * p + 1][1],
                      bS + bOff[p] + kk * 32);
#pragma unroll
            for (int mi = 0; mi < 2; mi++)
#pragma unroll
                for (int ni = 0; ni < 4; ni++)
                    MMA_F16(acc[mi][ni], a[mi], b[ni]);
        }

        const int col_base = i * 64 + wn * 32;
#pragma unroll
        for (int mi = 0; mi < 2; mi++) {
#pragma unroll
            for (int ni = 0; ni < 4; ni++) {
                int r0 = row_base + mi * 16 + g;
                int c = col_base + ni * 8 + 2 * tg;
                *reinterpret_cast<uint32_t*>(C + (size_t)r0 * N_SEQ + c) =
                    pack_h2(acc[mi][ni][0] * SCALE, acc[mi][ni][1] * SCALE);
                *reinterpret_cast<uint32_t*>(C + (size_t)(r0 + 8) * N_SEQ + c) =
                    pack_h2(acc[mi][ni][2] * SCALE, acc[mi][ni][3] * SCALE);
            }
        }
        st++; if (st == 3) st = 0;
    }
}

// ---------------------------------------------------------------------------
// elementwise fp16 round of x
// ---------------------------------------------------------------------------
__global__ void round_x_f16(const float* __restrict__ in, __half* __restrict__ out)
{
    int i = blockIdx.x * 256 + threadIdx.x;
    float4 v = reinterpret_cast<const float4*>(in)[i];
    uint2 p;
    p.x = pack_h2(v.x, v.y);
    p.y = pack_h2(v.z, v.w);
    reinterpret_cast<uint2*>(out)[i] = p;
}

// ---------------------------------------------------------------------------
// 32x32 tiled transpose fp32 -> fp16
// ---------------------------------------------------------------------------
__global__ void transpose2d(const float* __restrict__ in, __half* __restrict__ out,
                            int R, int Cc)
{
    __shared__ float t[32][33];
    int c0 = blockIdx.x * 32, r0 = blockIdx.y * 32;
    int x = threadIdx.x, y = threadIdx.y;
#pragma unroll
    for (int i = 0; i < 4; i++)
        t[y + i * 8][x] = in[(size_t)(r0 + y + i * 8) * Cc + c0 + x];
    __syncthreads();
#pragma unroll
    for (int i = 0; i < 4; i++)
        out[(size_t)(c0 + y + i * 8) * R + r0 + x] = __float2half_rn(t[x][y + i * 8]);
}

// V slice of g_qkv (half) -> g_vT[z][d][m] (half)
__global__ void transpose_v()
{
    __shared__ float t[32][33];
    int z = blockIdx.z;
    int b = z / H_HEAD, h = z % H_HEAD;
    const __half* in = g_qkv + (size_t)b * N_SEQ * QKV_LD + 2 * C_DIM + h * D_HEAD;
    __half* out = g_vT + (size_t)z * D_HEAD * N_SEQ;
    int m0 = blockIdx.x * 32, d0 = blockIdx.y * 32;
    int x = threadIdx.x, y = threadIdx.y;
#pragma unroll
    for (int i = 0; i < 4; i++)
        t[y + i * 8][x] = __half2float(in[(size_t)(m0 + y + i * 8) * QKV_LD + d0 + x]);
    __syncthreads();
#pragma unroll
    for (int i = 0; i < 4; i++)
        out[(size_t)(d0 + y + i * 8) * N_SEQ + m0 + x] = __float2half_rn(t[x][y + i * 8]);
}

// ---------------------------------------------------------------------------
// Fused pre-mix (w_l) -> softmax over m -> post-mix (w_w).
// Reads fp16 scores; writes fp16 g_attn. One CTA per (b, n).
// ---------------------------------------------------------------------------
__global__ __launch_bounds__(256) void mixsoftmax_kernel(
    const float* __restrict__ w_l, const float* __restrict__ b_l,
    const float* __restrict__ w_w, const float* __restrict__ b_w)
{
    __shared__ float swl[144], sww[144], sbl[12], sbw[12];
    __shared__ float red[8][12];
    const int tid = threadIdx.x;
    if (tid < 144) { swl[tid] = w_l[tid]; sww[tid] = w_w[tid]; }
    if (tid < 12)  { sbl[tid] = b_l[tid]; sbw[tid] = b_w[tid]; }
    __syncthreads();

    const __half* sp = reinterpret_cast<const __half*>(g_scores);
    const int bn = blockIdx.x;
    const int b = bn >> 10, n = bn & 1023;
    const size_t base = ((size_t)b * H_HEAD * N_SEQ + n) * N_SEQ;
    const int m0 = tid * 4;
    const int lane = tid & 31, wid = tid >> 5;

    float t[12][4];
#pragma unroll
    for (int g = 0; g < 12; g++) {
        float bl = sbl[g];
        t[g][0] = bl; t[g][1] = bl; t[g][2] = bl; t[g][3] = bl;
    }
#pragma unroll
    for (int h = 0; h < 12; h++) {
        uint2 u = *reinterpret_cast<const uint2*>(sp + base + (size_t)h * N_SEQ * N_SEQ + m0);
        float2 f01 = __half22float2(*reinterpret_cast<const __half2*>(&u.x));
        float2 f23 = __half22float2(*reinterpret_cast<const __half2*>(&u.y));
#pragma unroll
        for (int g = 0; g < 12; g++) {
            float wl = swl[h * 12 + g];
            t[g][0] = fmaf(f01.x, wl, t[g][0]);
            t[g][1] = fmaf(f01.y, wl, t[g][1]);
            t[g][2] = fmaf(f23.x, wl, t[g][2]);
            t[g][3] = fmaf(f23.y, wl, t[g][3]);
        }
    }

    float lmax[12];
#pragma unroll
    for (int g = 0; g < 12; g++) {
        float v = fmaxf(fmaxf(t[g][0], t[g][1]), fmaxf(t[g][2], t[g][3]));
#pragma unroll
        for (int o = 16; o > 0; o >>= 1) v = fmaxf(v, __shfl_xor_sync(0xffffffffu, v, o));
        if (lane == 0) red[wid][g] = v;
    }
    __syncthreads();
#pragma unroll
    for (int g = 0; g < 12; g++) {
        float v = red[0][g];
#pragma unroll
        for (int w = 1; w < 8; w++) v = fmaxf(v, red[w][g]);
        lmax[g] = v;
    }
    __syncthreads();

    float lsum[12];
#pragma unroll
    for (int g = 0; g < 12; g++) {
        t[g][0] = __expf(t[g][0] - lmax[g]);
        t[g][1] = __expf(t[g][1] - lmax[g]);
        t[g][2] = __expf(t[g][2] - lmax[g]);
        t[g][3] = __expf(t[g][3] - lmax[g]);
        float v = (t[g][0] + t[g][1]) + (t[g][2] + t[g][3]);
#pragma unroll
        for (int o = 16; o > 0; o >>= 1) v += __shfl_xor_sync(0xffffffffu, v, o);
        if (lane == 0) red[wid][g] = v;
    }
    __syncthreads();
#pragma unroll
    for (int g = 0; g < 12; g++) {
        float v = red[0][g];
#pragma unroll
        for (int w = 1; w < 8; w++) v += red[w][g];
        lsum[g] = 1.0f / v;
    }

#pragma unroll
    for (int g = 0; g < 12; g++) {
        t[g][0] *= lsum[g]; t[g][1] *= lsum[g]; t[g][2] *= lsum[g]; t[g][3] *= lsum[g];
    }

#pragma unroll
    for (int g = 0; g < 12; g++) {
        float o0 = sbw[g], o1 = sbw[g], o2 = sbw[g], o3 = sbw[g];
#pragma unroll
        for (int h = 0; h < 12; h++) {
            float ww = sww[h * 12 + g];
            o0 = fmaf(t[h][0], ww, o0);
            o1 = fmaf(t[h][1], ww, o1);
            o2 = fmaf(t[h][2], ww, o2);
            o3 = fmaf(t[h][3], ww, o3);
        }
        uint2 p;
        p.x = pack_h2(o0, o1);
        p.y = pack_h2(o2, o3);
        *reinterpret_cast<uint2*>(g_attn + base + (size_t)g * N_SEQ * N_SEQ + m0) = p;
    }
}

// ---------------------------------------------------------------------------
extern "C" void kernel_launch(void* const* d_in, const int* in_sizes, int n_in,
                              void* d_out, int out_size)
{
    const float* x      = (const float*)d_in[0];
    const float* w_qkv  = (const float*)d_in[1];
    const float* b_qkv  = (const float*)d_in[2];
    const float* w_l    = (const float*)d_in[3];
    const float* b_l    = (const float*)d_in[4];
    const float* w_w    = (const float*)d_in[5];
    const float* b_w    = (const float*)d_in[6];
    const float* w_proj = (const float*)d_in[7];
    const float* b_proj = (const float*)d_in[8];
    float* out = (float*)d_out;

    __half *xh_p, *qkv_p, *attn_p, *av_p, *vT_p, *wqkvT_p, *wprojT_p;
    float *scores_p;
    cudaGetSymbolAddress((void**)&xh_p, g_xh);
    cudaGetSymbolAddress((void**)&qkv_p, g_qkv);
    cudaGetSymbolAddress((void**)&scores_p, g_scores);
    cudaGetSymbolAddress((void**)&attn_p, g_attn);
    cudaGetSymbolAddress((void**)&av_p, g_av);
    cudaGetSymbolAddress((void**)&vT_p, g_vT);
    cudaGetSymbolAddress((void**)&wqkvT_p, g_wqkvT);
    cudaGetSymbolAddress((void**)&wprojT_p, g_wprojT);

    // dynamic smem
    const int smem128 = 3 * (128 + 128) * 72 * 2;   // 110592 (QKV / proj)
    const int smem64  = 3 * (128 + 64) * 72 * 2;    // 82944  (AV)
    const int smemQK  = (128 + 3 * 64) * 72 * 2;    // 46080  (qk: q + 3 k stages)
    cudaFuncSetAttribute(gemm_f16<128, true >, cudaFuncAttributeMaxDynamicSharedMemorySize, smem128);
    cudaFuncSetAttribute(gemm_f16<128, false>, cudaFuncAttributeMaxDynamicSharedMemorySize, smem128);
    cudaFuncSetAttribute(gemm_f16<64,  true >, cudaFuncAttributeMaxDynamicSharedMemorySize, smem64);
    cudaFuncSetAttribute(qk_kernel, cudaFuncAttributeMaxDynamicSharedMemorySize, smemQK);

    // 0) fp16 conversions: x, transposed weights
    round_x_f16<<<(B_SZ * N_SEQ * C_DIM / 4) / 256, 256>>>(x, xh_p);
    transpose2d<<<dim3(QKV_LD / 32, C_DIM / 32), dim3(32, 8)>>>(w_qkv, wqkvT_p, C_DIM, QKV_LD);
    transpose2d<<<dim3(C_DIM / 32, C_DIM / 32), dim3(32, 8)>>>(w_proj, wprojT_p, C_DIM, C_DIM);

    const long long SH = (long long)N_SEQ * N_SEQ;
    const long long VH = (long long)D_HEAD * N_SEQ;

    // 1) QKV projection: [8192,768] @ wqkvT^T + bias -> fp16 qkv
    gemm_f16<128, true><<<dim3(QKV_LD / 128, B_SZ * N_SEQ / 128, 1), 256, smem128>>>(
        xh_p, wqkvT_p, b_qkv, qkv_p, C_DIM, C_DIM, C_DIM, QKV_LD,
        0, 0, 0, 0, 0, 0, 1.0f);

    // 2) transpose V slices into g_vT[z][d][m]
    transpose_v<<<dim3(N_SEQ / 32, D_HEAD / 32, B_SZ * H_HEAD), dim3(32, 8)>>>();

    // 3) scores = SCALE * q @ k^T -> fp16 (q-persistent kernel, offset fixed)
    qk_kernel<<<dim3(N_SEQ / 128, 1, B_SZ * H_HEAD), 256, smemQK>>>();

    // 4) fused talking-heads pre-mix + softmax + post-mix -> fp16 attn
    mixsoftmax_kernel<<<B_SZ * N_SEQ, 256>>>(w_l, b_l, w_w, b_w);

    // 5) av = attn @ vT^T -> fp16 av (full batch, z=96)
    gemm_f16<64, true><<<dim3(1, N_SEQ / 128, B_SZ * H_HEAD), 256, smem64>>>(
        attn_p, vT_p, nullptr, av_p, N_SEQ, N_SEQ, N_SEQ, C_DIM,
        H_HEAD * SH, SH, H_HEAD * VH, VH, (long long)N_SEQ * C_DIM, D_HEAD, 1.0f);

    // 6) out = av @ wprojT^T + bias (fp32 out)
    gemm_f16<128, false><<<dim3(C_DIM / 128, B_SZ * N_SEQ / 128, 1), 256, smem128>>>(
        av_p, wprojT_p, b_proj, out, C_DIM, C_DIM, C_DIM, C_DIM,
        0, 0, 0, 0, 0, 0, 1.0f);
}